// round 1
// baseline (speedup 1.0000x reference)
#include <cuda_runtime.h>
#include <math.h>

// Problem constants
#define BATCH 4
#define SEQ 4096
#define DMODEL 1024
#define NHEAD 16
#define DH 64            // DMODEL / NHEAD
#define MTOK (BATCH*SEQ) // 16384 tokens

// ----- scratch (allocation-free rule: __device__ globals) -----
__device__ float g_q [(size_t)MTOK * DMODEL];
__device__ float g_k [(size_t)MTOK * DMODEL];
__device__ float g_v [(size_t)MTOK * DMODEL];
__device__ float g_ao[(size_t)MTOK * DMODEL];

// ================= SGEMM: C[M,N] = A[M,K] @ W[N,K]^T + bias[N] =================
// Both A and W are K-contiguous (NT gemm). M,N multiples of 128, K multiple of 16.
#define BM 128
#define BN 128
#define BK 16
#define TM 8
#define TN 8
#define SPAD 4

__global__ __launch_bounds__(256, 2) void sgemm_nt_bias(
    const float* __restrict__ A,    // [M,K]
    const float* __restrict__ W,    // [N,K]
    const float* __restrict__ bias, // [N]
    float* __restrict__ C,          // [M,N]
    int M, int N, int K)
{
    __shared__ float As[BK][BM + SPAD];
    __shared__ float Bs[BK][BN + SPAD];

    const int tid = threadIdx.x;
    const int tx  = tid & 15;   // 0..15 -> N groups
    const int ty  = tid >> 4;   // 0..15 -> M groups

    const int m0 = blockIdx.y * BM;
    const int n0 = blockIdx.x * BN;

    float acc[TM][TN];
#pragma unroll
    for (int i = 0; i < TM; i++)
#pragma unroll
        for (int j = 0; j < TN; j++) acc[i][j] = 0.0f;

    // Each tile is BM x BK = 2048 floats = 512 float4; 256 threads load 2 each.
    for (int k0 = 0; k0 < K; k0 += BK) {
#pragma unroll
        for (int l = 0; l < 2; l++) {
            int f   = tid + l * 256;
            int row = f >> 2;      // 0..127
            int c4  = f & 3;       // which float4 within the 16-wide K slab
            float4 a = *(const float4*)(A + (size_t)(m0 + row) * K + k0 + c4 * 4);
            As[c4 * 4 + 0][row] = a.x;
            As[c4 * 4 + 1][row] = a.y;
            As[c4 * 4 + 2][row] = a.z;
            As[c4 * 4 + 3][row] = a.w;
            float4 b = *(const float4*)(W + (size_t)(n0 + row) * K + k0 + c4 * 4);
            Bs[c4 * 4 + 0][row] = b.x;
            Bs[c4 * 4 + 1][row] = b.y;
            Bs[c4 * 4 + 2][row] = b.z;
            Bs[c4 * 4 + 3][row] = b.w;
        }
        __syncthreads();

#pragma unroll
        for (int kk = 0; kk < BK; kk++) {
            float ra[TM], rb[TN];
#pragma unroll
            for (int i = 0; i < TM; i += 4) {
                float4 t = *(const float4*)&As[kk][ty * TM + i];
                ra[i + 0] = t.x; ra[i + 1] = t.y; ra[i + 2] = t.z; ra[i + 3] = t.w;
            }
#pragma unroll
            for (int j = 0; j < TN; j += 4) {
                float4 t = *(const float4*)&Bs[kk][tx * TN + j];
                rb[j + 0] = t.x; rb[j + 1] = t.y; rb[j + 2] = t.z; rb[j + 3] = t.w;
            }
#pragma unroll
            for (int i = 0; i < TM; i++)
#pragma unroll
                for (int j = 0; j < TN; j++)
                    acc[i][j] = fmaf(ra[i], rb[j], acc[i][j]);
        }
        __syncthreads();
    }

    // Epilogue: add bias, vectorized stores.
#pragma unroll
    for (int i = 0; i < TM; i++) {
        int m = m0 + ty * TM + i;
#pragma unroll
        for (int j = 0; j < TN; j += 4) {
            int n = n0 + tx * TN + j;
            float4 r;
            r.x = acc[i][j + 0] + bias[n + 0];
            r.y = acc[i][j + 1] + bias[n + 1];
            r.z = acc[i][j + 2] + bias[n + 2];
            r.w = acc[i][j + 3] + bias[n + 3];
            *(float4*)(C + (size_t)m * N + n) = r;
        }
    }
}

// ================= Per-token attention =================
// For token t: q,k,v rows of 1024 floats viewed as [64][16] with d = i*16 + h.
// scores[i][j] = 32 * sum_h q[i][h]*k[j][h]; softmax over j; out[i][h] = sum_j a*v[j][h].
// One block per token, 64 threads; thread i owns score row i entirely in registers.
__global__ __launch_bounds__(64) void attn_per_token(
    const float* __restrict__ q,
    const float* __restrict__ k,
    const float* __restrict__ v,
    float* __restrict__ out)
{
    const int t = blockIdx.x;
    const int i = threadIdx.x;   // 0..63

    __shared__ float sk[DMODEL];
    __shared__ float sv[DMODEL];

    const float* kt = k + (size_t)t * DMODEL;
    const float* vt = v + (size_t)t * DMODEL;
    // 1024 floats = 256 float4; 64 threads load 4 each.
#pragma unroll
    for (int f = i; f < 256; f += 64) {
        ((float4*)sk)[f] = ((const float4*)kt)[f];
        ((float4*)sv)[f] = ((const float4*)vt)[f];
    }
    __syncthreads();

    float qi[NHEAD];
    const float* qt = q + (size_t)t * DMODEL + i * NHEAD;
#pragma unroll
    for (int h4 = 0; h4 < NHEAD; h4 += 4) {
        float4 tq = *(const float4*)(qt + h4);
        qi[h4 + 0] = tq.x; qi[h4 + 1] = tq.y; qi[h4 + 2] = tq.z; qi[h4 + 3] = tq.w;
    }

    float sc[DH];
#pragma unroll
    for (int j = 0; j < DH; j++) {
        float s = 0.0f;
#pragma unroll
        for (int h = 0; h < NHEAD; h++)
            s = fmaf(qi[h], sk[j * NHEAD + h], s);
        sc[j] = s * 32.0f;   // * sqrt(D), faithful quirk: multiply
    }

    // Row softmax — fully thread-local.
    float mx = sc[0];
#pragma unroll
    for (int j = 1; j < DH; j++) mx = fmaxf(mx, sc[j]);
    float sum = 0.0f;
#pragma unroll
    for (int j = 0; j < DH; j++) {
        sc[j] = expf(sc[j] - mx);
        sum += sc[j];
    }
    const float inv = 1.0f / sum;

    float o[NHEAD];
#pragma unroll
    for (int h = 0; h < NHEAD; h++) o[h] = 0.0f;
#pragma unroll
    for (int j = 0; j < DH; j++) {
        float a = sc[j] * inv;
#pragma unroll
        for (int h = 0; h < NHEAD; h++)
            o[h] = fmaf(a, sv[j * NHEAD + h], o[h]);
    }

    float* ot = out + (size_t)t * DMODEL + i * NHEAD;
#pragma unroll
    for (int h4 = 0; h4 < NHEAD; h4 += 4) {
        float4 r;
        r.x = o[h4 + 0]; r.y = o[h4 + 1]; r.z = o[h4 + 2]; r.w = o[h4 + 3];
        *(float4*)(ot + h4) = r;
    }
}

// ================= launch =================
extern "C" void kernel_launch(void* const* d_in, const int* in_sizes, int n_in,
                              void* d_out, int out_size)
{
    const float* query = (const float*)d_in[0];
    const float* key_  = (const float*)d_in[1];
    const float* value = (const float*)d_in[2];
    const float* Wq    = (const float*)d_in[3];
    const float* bq    = (const float*)d_in[4];
    const float* Wk    = (const float*)d_in[5];
    const float* bk    = (const float*)d_in[6];
    const float* Wv    = (const float*)d_in[7];
    const float* bv    = (const float*)d_in[8];
    const float* Wo    = (const float*)d_in[9];
    const float* bo    = (const float*)d_in[10];
    float* out = (float*)d_out;

    float *q, *k, *v, *ao;
    cudaGetSymbolAddress((void**)&q,  g_q);
    cudaGetSymbolAddress((void**)&k,  g_k);
    cudaGetSymbolAddress((void**)&v,  g_v);
    cudaGetSymbolAddress((void**)&ao, g_ao);

    const int M = MTOK;     // 16384
    const int N = DMODEL;   // 1024
    const int K = DMODEL;   // 1024

    dim3 grid(N / BN, M / BM);  // (8, 128)
    dim3 block(256);

    sgemm_nt_bias<<<grid, block>>>(query, Wq, bq, q, M, N, K);
    sgemm_nt_bias<<<grid, block>>>(key_,  Wk, bk, k, M, N, K);
    sgemm_nt_bias<<<grid, block>>>(value, Wv, bv, v, M, N, K);

    attn_per_token<<<MTOK, 64>>>(q, k, v, ao);

    sgemm_nt_bias<<<grid, block>>>(ao, Wo, bo, out, M, N, K);
}

// round 3
// speedup vs baseline: 2.6123x; 2.6123x over previous
#include <cuda_runtime.h>
#include <cuda_bf16.h>
#include <math.h>
#include <stdint.h>

// ---------------- problem constants ----------------
#define BATCH 4
#define SEQ 4096
#define DMODEL 1024
#define NHEAD 16
#define DH 64
#define MTOK (BATCH*SEQ)   // 16384

// ---------------- scratch (__device__ globals; allocation-free rule) ------
__device__ float g_q [(size_t)MTOK * DMODEL];
__device__ float g_k [(size_t)MTOK * DMODEL];
__device__ float g_v [(size_t)MTOK * DMODEL];
__device__ float g_ao[(size_t)MTOK * DMODEL];
__device__ __nv_bfloat16 g_xh[(size_t)MTOK * DMODEL];
__device__ __nv_bfloat16 g_xl[(size_t)MTOK * DMODEL];
__device__ __nv_bfloat16 g_wh[(size_t)DMODEL * DMODEL];
__device__ __nv_bfloat16 g_wl[(size_t)DMODEL * DMODEL];

// ---------------- small PTX helpers (base ISA only; no sm_103a features) --
__device__ __forceinline__ uint32_t smem_u32(const void* p) {
    uint32_t a;
    asm("{ .reg .u64 t; cvta.to.shared.u64 t, %1; cvt.u32.u64 %0, t; }" : "=r"(a) : "l"(p));
    return a;
}

#define CP_ASYNC16(saddr, gptr) \
    asm volatile("cp.async.cg.shared.global [%0], [%1], 16;" :: "r"((uint32_t)(saddr)), "l"(gptr))
#define CP_COMMIT() asm volatile("cp.async.commit_group;" ::: "memory")
#define CP_WAIT(n)  asm volatile("cp.async.wait_group %0;" :: "n"(n) : "memory")

#define LDSM_X4(r, addr) \
    asm volatile("ldmatrix.sync.aligned.m8n8.x4.shared.b16 {%0,%1,%2,%3}, [%4];" \
        : "=r"((r)[0]), "=r"((r)[1]), "=r"((r)[2]), "=r"((r)[3]) : "r"(addr))

__device__ __forceinline__ void mma16816(float* d, const uint32_t* a, const uint32_t* b) {
    asm volatile(
        "mma.sync.aligned.m16n8k16.row.col.f32.bf16.bf16.f32 "
        "{%0,%1,%2,%3}, {%4,%5,%6,%7}, {%8,%9}, {%0,%1,%2,%3};"
        : "+f"(d[0]), "+f"(d[1]), "+f"(d[2]), "+f"(d[3])
        : "r"(a[0]), "r"(a[1]), "r"(a[2]), "r"(a[3]), "r"(b[0]), "r"(b[1]));
}

// ---------------- split fp32 -> bf16 hi/lo ----------------
__global__ void __launch_bounds__(256) split_bf16_kernel(
    const float4* __restrict__ in, uint2* __restrict__ hi, uint2* __restrict__ lo, int n4)
{
    int i = blockIdx.x * blockDim.x + threadIdx.x;
    if (i >= n4) return;
    float4 x = in[i];
    __nv_bfloat162 h01 = __floats2bfloat162_rn(x.x, x.y);
    __nv_bfloat162 h23 = __floats2bfloat162_rn(x.z, x.w);
    float2 f01 = __bfloat1622float2(h01);
    float2 f23 = __bfloat1622float2(h23);
    __nv_bfloat162 l01 = __floats2bfloat162_rn(x.x - f01.x, x.y - f01.y);
    __nv_bfloat162 l23 = __floats2bfloat162_rn(x.z - f23.x, x.w - f23.y);
    uint2 H, L;
    H.x = *reinterpret_cast<unsigned int*>(&h01);
    H.y = *reinterpret_cast<unsigned int*>(&h23);
    L.x = *reinterpret_cast<unsigned int*>(&l01);
    L.y = *reinterpret_cast<unsigned int*>(&l23);
    hi[i] = H;
    lo[i] = L;
}

// ---------------- bf16x3 GEMM via mma.sync (HMMA) ----------------
// C[M,N] = A[M,K] @ W[N,K]^T + bias ; A = Ah+Al, W = Wh+Wl
// CTA tile 128x128, K-chunk 64 (128B rows, SW128 swizzle), 3-stage cp.async.
#define GBM 128
#define GBN 128
#define GBK 64
#define KDIM DMODEL
#define NCHUNK (KDIM/GBK)      // 16
#define STAGE_BYTES 65536      // Ah 16K | Al 16K | Bh 16K | Bl 16K
#define A_HI 0
#define A_LO 16384
#define B_HI 32768
#define B_LO 49152
#define NSTAGE 3
#define GSMEM_TOTAL (NSTAGE*STAGE_BYTES)   // 196608

__global__ void __launch_bounds__(256, 1) gemm_bf16x3(
    const __nv_bfloat16* __restrict__ Ah, const __nv_bfloat16* __restrict__ Al,
    const __nv_bfloat16* __restrict__ Wh, const __nv_bfloat16* __restrict__ Wl,
    const float* __restrict__ bias, float* __restrict__ C)
{
    extern __shared__ char smem[];
    const uint32_t sb = smem_u32(smem);
    const int tid = threadIdx.x;
    const int m0 = blockIdx.y * GBM;
    const int n0 = blockIdx.x * GBN;

    // warp layout: 4 (m) x 2 (n), warp tile 32 x 64
    const int l  = tid & 31;
    const int w  = tid >> 5;
    const int wm = (w & 3) * 32;
    const int wn = (w >> 2) * 64;

    // per-lane ldmatrix row/ksel decomposition
    const int rowA  = (l & 7) + ((l >> 3) & 1) * 8;   // +8 rows for matrices 1,3
    const int kselA = (l >> 4) & 1;                   // +16B for matrices 2,3
    const int rowB  = (l & 7) + ((l >> 4) & 1) * 8;   // +8 rows for matrices 2,3
    const int kselB = (l >> 3) & 1;                   // +16B for matrices 1,3

    float acc[2][8][4];
#pragma unroll
    for (int a = 0; a < 2; a++)
#pragma unroll
        for (int b = 0; b < 8; b++)
#pragma unroll
            for (int c = 0; c < 4; c++) acc[a][b][c] = 0.0f;

    // ---- stage loader: K-chunk c -> stage st ----
    auto load_chunk = [&](int st, int c) {
        uint32_t base = sb + st * STAGE_BYTES;
        int k0 = c * GBK;
#pragma unroll
        for (int it = 0; it < 4; it++) {
            int idx = tid + it * 256;          // 0..1023
            int r  = idx >> 3;
            int ch = idx & 7;
            uint32_t sw = (uint32_t)(r * 128 + ((ch ^ (r & 7)) * 16));
            size_t gA = (size_t)(m0 + r) * KDIM + k0 + ch * 8;
            size_t gB = (size_t)(n0 + r) * KDIM + k0 + ch * 8;
            CP_ASYNC16(base + A_HI + sw, Ah + gA);
            CP_ASYNC16(base + A_LO + sw, Al + gA);
            CP_ASYNC16(base + B_HI + sw, Wh + gB);
            CP_ASYNC16(base + B_LO + sw, Wl + gB);
        }
    };

    // ---- compute one K-chunk (4 k16 steps) from stage st ----
    auto compute_chunk = [&](int st) {
        uint32_t base = sb + st * STAGE_BYTES;
#pragma unroll
        for (int s = 0; s < 4; s++) {
            uint32_t a_h[2][4], a_l[2][4], b_h[4][4], b_l[4][4];
#pragma unroll
            for (int mt = 0; mt < 2; mt++) {
                int row = wm + mt * 16 + rowA;
                int ch  = (s * 2 + kselA) ^ (row & 7);
                uint32_t off = (uint32_t)(row * 128 + ch * 16);
                LDSM_X4(a_h[mt], base + A_HI + off);
                LDSM_X4(a_l[mt], base + A_LO + off);
            }
#pragma unroll
            for (int ng = 0; ng < 4; ng++) {
                int row = wn + ng * 16 + rowB;
                int ch  = (s * 2 + kselB) ^ (row & 7);
                uint32_t off = (uint32_t)(row * 128 + ch * 16);
                LDSM_X4(b_h[ng], base + B_HI + off);
                LDSM_X4(b_l[ng], base + B_LO + off);
            }
#pragma unroll
            for (int mt = 0; mt < 2; mt++) {
#pragma unroll
                for (int ng = 0; ng < 4; ng++) {
                    // n8 group low  = regs 0,1 ; n8 group high = regs 2,3
                    mma16816(acc[mt][ng * 2 + 0], a_h[mt], &b_h[ng][0]);
                    mma16816(acc[mt][ng * 2 + 1], a_h[mt], &b_h[ng][2]);
                    mma16816(acc[mt][ng * 2 + 0], a_h[mt], &b_l[ng][0]);
                    mma16816(acc[mt][ng * 2 + 1], a_h[mt], &b_l[ng][2]);
                    mma16816(acc[mt][ng * 2 + 0], a_l[mt], &b_h[ng][0]);
                    mma16816(acc[mt][ng * 2 + 1], a_l[mt], &b_h[ng][2]);
                }
            }
        }
    };

    // ---- pipelined main loop ----
    load_chunk(0, 0); CP_COMMIT();
    load_chunk(1, 1); CP_COMMIT();

    for (int c = 0; c < NCHUNK; c++) {
        int st = c % NSTAGE;
        if (c + 2 < NCHUNK) {
            load_chunk((c + 2) % NSTAGE, c + 2); CP_COMMIT();
            CP_WAIT(2);
        } else {
            CP_WAIT(0);
        }
        __syncthreads();
        compute_chunk(st);
        __syncthreads();
    }

    // ---- epilogue: add bias, store fp32 ----
    const int g  = l >> 2;
    const int tg = l & 3;
#pragma unroll
    for (int mt = 0; mt < 2; mt++) {
#pragma unroll
        for (int nt = 0; nt < 8; nt++) {
            int n = n0 + wn + nt * 8 + tg * 2;
            float bx = bias[n], by = bias[n + 1];
            int mA = m0 + wm + mt * 16 + g;
            float2 lo = make_float2(acc[mt][nt][0] + bx, acc[mt][nt][1] + by);
            float2 hi = make_float2(acc[mt][nt][2] + bx, acc[mt][nt][3] + by);
            *(float2*)(C + (size_t)mA * DMODEL + n)       = lo;
            *(float2*)(C + (size_t)(mA + 8) * DMODEL + n) = hi;
        }
    }
}

// ---------------- per-token attention (2 tokens / 128-thread block) --------
__global__ __launch_bounds__(128) void attn_per_token(
    const float* __restrict__ q, const float* __restrict__ k,
    const float* __restrict__ v, float* __restrict__ out)
{
    const int half = threadIdx.x >> 6;
    const int t = blockIdx.x * 2 + half;
    const int i = threadIdx.x & 63;

    __shared__ float sk[2][DMODEL];
    __shared__ float sv[2][DMODEL];

    const float* kt = k + (size_t)t * DMODEL;
    const float* vt = v + (size_t)t * DMODEL;
#pragma unroll
    for (int f = i; f < 256; f += 64) {
        ((float4*)sk[half])[f] = ((const float4*)kt)[f];
        ((float4*)sv[half])[f] = ((const float4*)vt)[f];
    }
    __syncthreads();

    float qi[NHEAD];
    const float* qt = q + (size_t)t * DMODEL + i * NHEAD;
#pragma unroll
    for (int h4 = 0; h4 < NHEAD; h4 += 4) {
        float4 tq = *(const float4*)(qt + h4);
        qi[h4 + 0] = tq.x; qi[h4 + 1] = tq.y; qi[h4 + 2] = tq.z; qi[h4 + 3] = tq.w;
    }

    float sc[DH];
#pragma unroll
    for (int j = 0; j < DH; j++) {
        float s = 0.0f;
#pragma unroll
        for (int h = 0; h < NHEAD; h++)
            s = fmaf(qi[h], sk[half][j * NHEAD + h], s);
        sc[j] = s * 32.0f;   // * sqrt(D) — faithful quirk
    }

    float mx = sc[0];
#pragma unroll
    for (int j = 1; j < DH; j++) mx = fmaxf(mx, sc[j]);
    float sum = 0.0f;
#pragma unroll
    for (int j = 0; j < DH; j++) { sc[j] = expf(sc[j] - mx); sum += sc[j]; }
    const float inv = 1.0f / sum;

    float o[NHEAD];
#pragma unroll
    for (int h = 0; h < NHEAD; h++) o[h] = 0.0f;
#pragma unroll
    for (int j = 0; j < DH; j++) {
        float a = sc[j] * inv;
#pragma unroll
        for (int h = 0; h < NHEAD; h++)
            o[h] = fmaf(a, sv[half][j * NHEAD + h], o[h]);
    }

    float* ot = out + (size_t)t * DMODEL + i * NHEAD;
#pragma unroll
    for (int h4 = 0; h4 < NHEAD; h4 += 4) {
        float4 r;
        r.x = o[h4 + 0]; r.y = o[h4 + 1]; r.z = o[h4 + 2]; r.w = o[h4 + 3];
        *(float4*)(ot + h4) = r;
    }
}

// ---------------- launch ----------------
extern "C" void kernel_launch(void* const* d_in, const int* in_sizes, int n_in,
                              void* d_out, int out_size)
{
    const float* query = (const float*)d_in[0];
    const float* key_  = (const float*)d_in[1];
    const float* value = (const float*)d_in[2];
    const float* Wq    = (const float*)d_in[3];
    const float* bq    = (const float*)d_in[4];
    const float* Wk    = (const float*)d_in[5];
    const float* bk    = (const float*)d_in[6];
    const float* Wv    = (const float*)d_in[7];
    const float* bv    = (const float*)d_in[8];
    const float* Wo    = (const float*)d_in[9];
    const float* bo    = (const float*)d_in[10];
    float* out = (float*)d_out;

    float *q, *k, *v, *ao;
    __nv_bfloat16 *xh, *xl, *wh, *wl;
    cudaGetSymbolAddress((void**)&q,  g_q);
    cudaGetSymbolAddress((void**)&k,  g_k);
    cudaGetSymbolAddress((void**)&v,  g_v);
    cudaGetSymbolAddress((void**)&ao, g_ao);
    cudaGetSymbolAddress((void**)&xh, g_xh);
    cudaGetSymbolAddress((void**)&xl, g_xl);
    cudaGetSymbolAddress((void**)&wh, g_wh);
    cudaGetSymbolAddress((void**)&wl, g_wl);

    cudaFuncSetAttribute(gemm_bf16x3, cudaFuncAttributeMaxDynamicSharedMemorySize, GSMEM_TOTAL);

    const int nAct4 = MTOK * DMODEL / 4;
    const int nW4   = DMODEL * DMODEL / 4;
    dim3 cblkA((nAct4 + 255) / 256), cblkW((nW4 + 255) / 256);
    dim3 ggrid(DMODEL / GBN, MTOK / GBM);   // (8, 128)

    // Q projection
    split_bf16_kernel<<<cblkA, 256>>>((const float4*)query, (uint2*)xh, (uint2*)xl, nAct4);
    split_bf16_kernel<<<cblkW, 256>>>((const float4*)Wq, (uint2*)wh, (uint2*)wl, nW4);
    gemm_bf16x3<<<ggrid, 256, GSMEM_TOTAL>>>(xh, xl, wh, wl, bq, q);
    // K projection
    split_bf16_kernel<<<cblkA, 256>>>((const float4*)key_, (uint2*)xh, (uint2*)xl, nAct4);
    split_bf16_kernel<<<cblkW, 256>>>((const float4*)Wk, (uint2*)wh, (uint2*)wl, nW4);
    gemm_bf16x3<<<ggrid, 256, GSMEM_TOTAL>>>(xh, xl, wh, wl, bk, k);
    // V projection
    split_bf16_kernel<<<cblkA, 256>>>((const float4*)value, (uint2*)xh, (uint2*)xl, nAct4);
    split_bf16_kernel<<<cblkW, 256>>>((const float4*)Wv, (uint2*)wh, (uint2*)wl, nW4);
    gemm_bf16x3<<<ggrid, 256, GSMEM_TOTAL>>>(xh, xl, wh, wl, bv, v);

    // per-token attention
    attn_per_token<<<MTOK / 2, 128>>>(q, k, v, ao);

    // output projection
    split_bf16_kernel<<<cblkA, 256>>>((const float4*)ao, (uint2*)xh, (uint2*)xl, nAct4);
    split_bf16_kernel<<<cblkW, 256>>>((const float4*)Wo, (uint2*)wh, (uint2*)wl, nW4);
    gemm_bf16x3<<<ggrid, 256, GSMEM_TOTAL>>>(xh, xl, wh, wl, bo, out);
}

// round 4
// speedup vs baseline: 2.6764x; 1.0245x over previous
#include <cuda_runtime.h>
#include <cuda_bf16.h>
#include <math.h>
#include <stdint.h>

// ---------------- problem constants ----------------
#define BATCH 4
#define SEQ 4096
#define DMODEL 1024
#define NHEAD 16
#define DH 64
#define MTOK (BATCH*SEQ)   // 16384

// ---------------- scratch (__device__ globals; allocation-free rule) ------
__device__ float g_q [(size_t)MTOK * DMODEL];
__device__ float g_k [(size_t)MTOK * DMODEL];
__device__ float g_v [(size_t)MTOK * DMODEL];
__device__ __nv_bfloat16 g_xh[(size_t)MTOK * DMODEL];   // act hi split / ao hi split
__device__ __nv_bfloat16 g_xl[(size_t)MTOK * DMODEL];   // act lo split / ao lo split
__device__ __nv_bfloat16 g_wh[(size_t)DMODEL * DMODEL];
__device__ __nv_bfloat16 g_wl[(size_t)DMODEL * DMODEL];

// ---------------- small PTX helpers (base ISA only) ----------------
__device__ __forceinline__ uint32_t smem_u32(const void* p) {
    uint32_t a;
    asm("{ .reg .u64 t; cvta.to.shared.u64 t, %1; cvt.u32.u64 %0, t; }" : "=r"(a) : "l"(p));
    return a;
}

#define CP_ASYNC16(saddr, gptr) \
    asm volatile("cp.async.cg.shared.global [%0], [%1], 16;" :: "r"((uint32_t)(saddr)), "l"(gptr))
#define CP_COMMIT() asm volatile("cp.async.commit_group;" ::: "memory")
#define CP_WAIT(n)  asm volatile("cp.async.wait_group %0;" :: "n"(n) : "memory")

#define LDSM_X4(r, addr) \
    asm volatile("ldmatrix.sync.aligned.m8n8.x4.shared.b16 {%0,%1,%2,%3}, [%4];" \
        : "=r"((r)[0]), "=r"((r)[1]), "=r"((r)[2]), "=r"((r)[3]) : "r"(addr))

__device__ __forceinline__ void mma16816(float* d, const uint32_t* a, const uint32_t* b) {
    asm volatile(
        "mma.sync.aligned.m16n8k16.row.col.f32.bf16.bf16.f32 "
        "{%0,%1,%2,%3}, {%4,%5,%6,%7}, {%8,%9}, {%0,%1,%2,%3};"
        : "+f"(d[0]), "+f"(d[1]), "+f"(d[2]), "+f"(d[3])
        : "r"(a[0]), "r"(a[1]), "r"(a[2]), "r"(a[3]), "r"(b[0]), "r"(b[1]));
}

// ---------------- split fp32 -> bf16 hi/lo ----------------
__global__ void __launch_bounds__(256) split_bf16_kernel(
    const float4* __restrict__ in, uint2* __restrict__ hi, uint2* __restrict__ lo, int n4)
{
    int i = blockIdx.x * blockDim.x + threadIdx.x;
    if (i >= n4) return;
    float4 x = in[i];
    __nv_bfloat162 h01 = __floats2bfloat162_rn(x.x, x.y);
    __nv_bfloat162 h23 = __floats2bfloat162_rn(x.z, x.w);
    float2 f01 = __bfloat1622float2(h01);
    float2 f23 = __bfloat1622float2(h23);
    __nv_bfloat162 l01 = __floats2bfloat162_rn(x.x - f01.x, x.y - f01.y);
    __nv_bfloat162 l23 = __floats2bfloat162_rn(x.z - f23.x, x.w - f23.y);
    uint2 H, L;
    H.x = *reinterpret_cast<unsigned int*>(&h01);
    H.y = *reinterpret_cast<unsigned int*>(&h23);
    L.x = *reinterpret_cast<unsigned int*>(&l01);
    L.y = *reinterpret_cast<unsigned int*>(&l23);
    hi[i] = H;
    lo[i] = L;
}

// ---------------- bf16x3 GEMM via mma.sync (HMMA) ----------------
// C[M,N] = A[M,K] @ W[N,K]^T + bias ; A = Ah+Al, W = Wh+Wl
// CTA tile 128x128, K-chunk 64 (128B rows, SW128 swizzle), 3-stage cp.async.
// Single barrier per chunk; prefetch issued after barrier so copies overlap MMAs.
#define GBM 128
#define GBN 128
#define GBK 64
#define KDIM DMODEL
#define NCHUNK (KDIM/GBK)      // 16
#define STAGE_BYTES 65536      // Ah 16K | Al 16K | Bh 16K | Bl 16K
#define A_HI 0
#define A_LO 16384
#define B_HI 32768
#define B_LO 49152
#define NSTAGE 3
#define GSMEM_TOTAL (NSTAGE*STAGE_BYTES)   // 196608

__global__ void __launch_bounds__(256, 1) gemm_bf16x3(
    const __nv_bfloat16* __restrict__ Ah, const __nv_bfloat16* __restrict__ Al,
    const __nv_bfloat16* __restrict__ Wh, const __nv_bfloat16* __restrict__ Wl,
    const float* __restrict__ bias, float* __restrict__ C)
{
    extern __shared__ char smem[];
    const uint32_t sb = smem_u32(smem);
    const int tid = threadIdx.x;
    const int m0 = blockIdx.y * GBM;
    const int n0 = blockIdx.x * GBN;

    // warp layout: 4 (m) x 2 (n), warp tile 32 x 64
    const int l  = tid & 31;
    const int w  = tid >> 5;
    const int wm = (w & 3) * 32;
    const int wn = (w >> 2) * 64;

    const int rowA  = (l & 7) + ((l >> 3) & 1) * 8;
    const int kselA = (l >> 4) & 1;
    const int rowB  = (l & 7) + ((l >> 4) & 1) * 8;
    const int kselB = (l >> 3) & 1;

    float acc[2][8][4];
#pragma unroll
    for (int a = 0; a < 2; a++)
#pragma unroll
        for (int b = 0; b < 8; b++)
#pragma unroll
            for (int c = 0; c < 4; c++) acc[a][b][c] = 0.0f;

    auto load_chunk = [&](int st, int c) {
        uint32_t base = sb + st * STAGE_BYTES;
        int k0 = c * GBK;
#pragma unroll
        for (int it = 0; it < 4; it++) {
            int idx = tid + it * 256;
            int r  = idx >> 3;
            int ch = idx & 7;
            uint32_t sw = (uint32_t)(r * 128 + ((ch ^ (r & 7)) * 16));
            size_t gA = (size_t)(m0 + r) * KDIM + k0 + ch * 8;
            size_t gB = (size_t)(n0 + r) * KDIM + k0 + ch * 8;
            CP_ASYNC16(base + A_HI + sw, Ah + gA);
            CP_ASYNC16(base + A_LO + sw, Al + gA);
            CP_ASYNC16(base + B_HI + sw, Wh + gB);
            CP_ASYNC16(base + B_LO + sw, Wl + gB);
        }
    };

    // compute one K-chunk (4 k16 steps); products outermost per step for acc ILP
    auto compute_chunk = [&](int st) {
        uint32_t base = sb + st * STAGE_BYTES;
#pragma unroll
        for (int s = 0; s < 4; s++) {
            uint32_t a_h[2][4], a_l[2][4], b_h[4][4], b_l[4][4];
#pragma unroll
            for (int mt = 0; mt < 2; mt++) {
                int row = wm + mt * 16 + rowA;
                int ch  = (s * 2 + kselA) ^ (row & 7);
                uint32_t off = (uint32_t)(row * 128 + ch * 16);
                LDSM_X4(a_h[mt], base + A_HI + off);
                LDSM_X4(a_l[mt], base + A_LO + off);
            }
#pragma unroll
            for (int ng = 0; ng < 4; ng++) {
                int row = wn + ng * 16 + rowB;
                int ch  = (s * 2 + kselB) ^ (row & 7);
                uint32_t off = (uint32_t)(row * 128 + ch * 16);
                LDSM_X4(b_h[ng], base + B_HI + off);
                LDSM_X4(b_l[ng], base + B_LO + off);
            }
            // p0: Ah*Bh  p1: Ah*Bl  p2: Al*Bh — 16 independent MMAs between
            // consecutive writes to the same accumulator.
#pragma unroll
            for (int p = 0; p < 3; p++) {
#pragma unroll
                for (int mt = 0; mt < 2; mt++) {
#pragma unroll
                    for (int ng = 0; ng < 4; ng++) {
                        const uint32_t* A = (p == 2) ? a_l[mt] : a_h[mt];
                        const uint32_t* B = (p == 1) ? b_l[ng] : b_h[ng];
                        mma16816(acc[mt][ng * 2 + 0], A, &B[0]);
                        mma16816(acc[mt][ng * 2 + 1], A, &B[2]);
                    }
                }
            }
        }
    };

    load_chunk(0, 0); CP_COMMIT();
    load_chunk(1, 1); CP_COMMIT();

    for (int c = 0; c < NCHUNK; c++) {
        int st = c % NSTAGE;
        if (c + 2 < NCHUNK) { CP_WAIT(1); } else { CP_WAIT(0); }
        __syncthreads();                       // all warps done with stage (c-1)
        if (c + 2 < NCHUNK) {                  // prefetch overlaps compute below
            load_chunk((c + 2) % NSTAGE, c + 2); CP_COMMIT();
        }
        compute_chunk(st);
    }

    // epilogue: add bias, store fp32
    const int g  = l >> 2;
    const int tg = l & 3;
#pragma unroll
    for (int mt = 0; mt < 2; mt++) {
#pragma unroll
        for (int nt = 0; nt < 8; nt++) {
            int n = n0 + wn + nt * 8 + tg * 2;
            float bx = bias[n], by = bias[n + 1];
            int mA = m0 + wm + mt * 16 + g;
            float2 lo = make_float2(acc[mt][nt][0] + bx, acc[mt][nt][1] + by);
            float2 hi = make_float2(acc[mt][nt][2] + bx, acc[mt][nt][3] + by);
            *(float2*)(C + (size_t)mA * DMODEL + n)       = lo;
            *(float2*)(C + (size_t)(mA + 8) * DMODEL + n) = hi;
        }
    }
}

// ---------------- per-token attention (2 tokens / 128-thread block) --------
// Writes output directly as bf16 hi/lo splits (A-operand of the O-projection).
__global__ __launch_bounds__(128) void attn_per_token(
    const float* __restrict__ q, const float* __restrict__ k,
    const float* __restrict__ v,
    __nv_bfloat16* __restrict__ aoh, __nv_bfloat16* __restrict__ aol)
{
    const int half = threadIdx.x >> 6;
    const int t = blockIdx.x * 2 + half;
    const int i = threadIdx.x & 63;

    __shared__ float sk[2][DMODEL];
    __shared__ float sv[2][DMODEL];

    const float* kt = k + (size_t)t * DMODEL;
    const float* vt = v + (size_t)t * DMODEL;
#pragma unroll
    for (int f = i; f < 256; f += 64) {
        ((float4*)sk[half])[f] = ((const float4*)kt)[f];
        ((float4*)sv[half])[f] = ((const float4*)vt)[f];
    }
    __syncthreads();

    float qi[NHEAD];
    const float* qt = q + (size_t)t * DMODEL + i * NHEAD;
#pragma unroll
    for (int h4 = 0; h4 < NHEAD; h4 += 4) {
        float4 tq = *(const float4*)(qt + h4);
        qi[h4 + 0] = tq.x; qi[h4 + 1] = tq.y; qi[h4 + 2] = tq.z; qi[h4 + 3] = tq.w;
    }

    float sc[DH];
#pragma unroll
    for (int j = 0; j < DH; j++) {
        float s = 0.0f;
#pragma unroll
        for (int h = 0; h < NHEAD; h++)
            s = fmaf(qi[h], sk[half][j * NHEAD + h], s);
        sc[j] = s * 32.0f;   // * sqrt(D) — faithful quirk
    }

    float mx = sc[0];
#pragma unroll
    for (int j = 1; j < DH; j++) mx = fmaxf(mx, sc[j]);
    float sum = 0.0f;
#pragma unroll
    for (int j = 0; j < DH; j++) { sc[j] = __expf(sc[j] - mx); sum += sc[j]; }
    const float inv = 1.0f / sum;

    float o[NHEAD];
#pragma unroll
    for (int h = 0; h < NHEAD; h++) o[h] = 0.0f;
#pragma unroll
    for (int j = 0; j < DH; j++) {
        float a = sc[j] * inv;
#pragma unroll
        for (int h = 0; h < NHEAD; h++)
            o[h] = fmaf(a, sv[half][j * NHEAD + h], o[h]);
    }

    // split epilogue: 16 fp32 -> 8x(bf16x2 hi) + 8x(bf16x2 lo), two 16B stores each
    uint32_t hi8[8], lo8[8];
#pragma unroll
    for (int p = 0; p < 8; p++) {
        float x = o[2 * p], y = o[2 * p + 1];
        __nv_bfloat162 h2 = __floats2bfloat162_rn(x, y);
        float2 hf = __bfloat1622float2(h2);
        __nv_bfloat162 l2 = __floats2bfloat162_rn(x - hf.x, y - hf.y);
        hi8[p] = *reinterpret_cast<uint32_t*>(&h2);
        lo8[p] = *reinterpret_cast<uint32_t*>(&l2);
    }
    size_t obase = (size_t)t * DMODEL + i * NHEAD;
    uint4 H0 = make_uint4(hi8[0], hi8[1], hi8[2], hi8[3]);
    uint4 H1 = make_uint4(hi8[4], hi8[5], hi8[6], hi8[7]);
    uint4 L0 = make_uint4(lo8[0], lo8[1], lo8[2], lo8[3]);
    uint4 L1 = make_uint4(lo8[4], lo8[5], lo8[6], lo8[7]);
    *(uint4*)(aoh + obase)     = H0;
    *(uint4*)(aoh + obase + 8) = H1;
    *(uint4*)(aol + obase)     = L0;
    *(uint4*)(aol + obase + 8) = L1;
}

// ---------------- launch ----------------
extern "C" void kernel_launch(void* const* d_in, const int* in_sizes, int n_in,
                              void* d_out, int out_size)
{
    const float* query = (const float*)d_in[0];
    const float* key_  = (const float*)d_in[1];
    const float* value = (const float*)d_in[2];
    const float* Wq    = (const float*)d_in[3];
    const float* bq    = (const float*)d_in[4];
    const float* Wk    = (const float*)d_in[5];
    const float* bk    = (const float*)d_in[6];
    const float* Wv    = (const float*)d_in[7];
    const float* bv    = (const float*)d_in[8];
    const float* Wo    = (const float*)d_in[9];
    const float* bo    = (const float*)d_in[10];
    float* out = (float*)d_out;

    float *q, *k, *v;
    __nv_bfloat16 *xh, *xl, *wh, *wl;
    cudaGetSymbolAddress((void**)&q,  g_q);
    cudaGetSymbolAddress((void**)&k,  g_k);
    cudaGetSymbolAddress((void**)&v,  g_v);
    cudaGetSymbolAddress((void**)&xh, g_xh);
    cudaGetSymbolAddress((void**)&xl, g_xl);
    cudaGetSymbolAddress((void**)&wh, g_wh);
    cudaGetSymbolAddress((void**)&wl, g_wl);

    cudaFuncSetAttribute(gemm_bf16x3, cudaFuncAttributeMaxDynamicSharedMemorySize, GSMEM_TOTAL);

    const int nAct4 = MTOK * DMODEL / 4;
    const int nW4   = DMODEL * DMODEL / 4;
    dim3 cblkA((nAct4 + 255) / 256), cblkW((nW4 + 255) / 256);
    dim3 ggrid(DMODEL / GBN, MTOK / GBM);   // (8, 128)

    // Q projection
    split_bf16_kernel<<<cblkA, 256>>>((const float4*)query, (uint2*)xh, (uint2*)xl, nAct4);
    split_bf16_kernel<<<cblkW, 256>>>((const float4*)Wq, (uint2*)wh, (uint2*)wl, nW4);
    gemm_bf16x3<<<ggrid, 256, GSMEM_TOTAL>>>(xh, xl, wh, wl, bq, q);
    // K projection
    split_bf16_kernel<<<cblkA, 256>>>((const float4*)key_, (uint2*)xh, (uint2*)xl, nAct4);
    split_bf16_kernel<<<cblkW, 256>>>((const float4*)Wk, (uint2*)wh, (uint2*)wl, nW4);
    gemm_bf16x3<<<ggrid, 256, GSMEM_TOTAL>>>(xh, xl, wh, wl, bk, k);
    // V projection
    split_bf16_kernel<<<cblkA, 256>>>((const float4*)value, (uint2*)xh, (uint2*)xl, nAct4);
    split_bf16_kernel<<<cblkW, 256>>>((const float4*)Wv, (uint2*)wh, (uint2*)wl, nW4);
    gemm_bf16x3<<<ggrid, 256, GSMEM_TOTAL>>>(xh, xl, wh, wl, bv, v);

    // attention: writes ao hi/lo splits directly into xh/xl (O-gemm A operand)
    attn_per_token<<<MTOK / 2, 128>>>(q, k, v, xh, xl);

    // output projection (no activation split kernel needed)
    split_bf16_kernel<<<cblkW, 256>>>((const float4*)Wo, (uint2*)wh, (uint2*)wl, nW4);
    gemm_bf16x3<<<ggrid, 256, GSMEM_TOTAL>>>(xh, xl, wh, wl, bo, out);
}

// round 5
// speedup vs baseline: 2.6767x; 1.0001x over previous
#include <cuda_runtime.h>
#include <cuda_bf16.h>
#include <math.h>
#include <stdint.h>

// ---------------- problem constants ----------------
#define BATCH 4
#define SEQ 4096
#define DMODEL 1024
#define NHEAD 16
#define DH 64
#define MTOK (BATCH*SEQ)   // 16384

// ---------------- scratch (__device__ globals; allocation-free rule) ------
__device__ float g_q [(size_t)MTOK * DMODEL];
__device__ float g_k [(size_t)MTOK * DMODEL];
__device__ float g_v [(size_t)MTOK * DMODEL];
__device__ __nv_bfloat16 g_xh[(size_t)MTOK * DMODEL];   // act hi split / ao hi split
__device__ __nv_bfloat16 g_xl[(size_t)MTOK * DMODEL];   // act lo split / ao lo split
__device__ __nv_bfloat16 g_wh[(size_t)DMODEL * DMODEL];
__device__ __nv_bfloat16 g_wl[(size_t)DMODEL * DMODEL];

// ---------------- small PTX helpers (base ISA only) ----------------
__device__ __forceinline__ uint32_t smem_u32(const void* p) {
    uint32_t a;
    asm("{ .reg .u64 t; cvta.to.shared.u64 t, %1; cvt.u32.u64 %0, t; }" : "=r"(a) : "l"(p));
    return a;
}

#define CP_ASYNC16(saddr, gptr) \
    asm volatile("cp.async.cg.shared.global [%0], [%1], 16;" :: "r"((uint32_t)(saddr)), "l"(gptr))
#define CP_COMMIT() asm volatile("cp.async.commit_group;" ::: "memory")
#define CP_WAIT(n)  asm volatile("cp.async.wait_group %0;" :: "n"(n) : "memory")

#define LDSM_X4(r, addr) \
    asm volatile("ldmatrix.sync.aligned.m8n8.x4.shared.b16 {%0,%1,%2,%3}, [%4];" \
        : "=r"((r)[0]), "=r"((r)[1]), "=r"((r)[2]), "=r"((r)[3]) : "r"(addr))

__device__ __forceinline__ void mma16816(float* d, const uint32_t* a, const uint32_t* b) {
    asm volatile(
        "mma.sync.aligned.m16n8k16.row.col.f32.bf16.bf16.f32 "
        "{%0,%1,%2,%3}, {%4,%5,%6,%7}, {%8,%9}, {%0,%1,%2,%3};"
        : "+f"(d[0]), "+f"(d[1]), "+f"(d[2]), "+f"(d[3])
        : "r"(a[0]), "r"(a[1]), "r"(a[2]), "r"(a[3]), "r"(b[0]), "r"(b[1]));
}

// ---------------- split fp32 -> bf16 hi/lo ----------------
__global__ void __launch_bounds__(256) split_bf16_kernel(
    const float4* __restrict__ in, uint2* __restrict__ hi, uint2* __restrict__ lo, int n4)
{
    int i = blockIdx.x * blockDim.x + threadIdx.x;
    if (i >= n4) return;
    float4 x = in[i];
    __nv_bfloat162 h01 = __floats2bfloat162_rn(x.x, x.y);
    __nv_bfloat162 h23 = __floats2bfloat162_rn(x.z, x.w);
    float2 f01 = __bfloat1622float2(h01);
    float2 f23 = __bfloat1622float2(h23);
    __nv_bfloat162 l01 = __floats2bfloat162_rn(x.x - f01.x, x.y - f01.y);
    __nv_bfloat162 l23 = __floats2bfloat162_rn(x.z - f23.x, x.w - f23.y);
    uint2 H, L;
    H.x = *reinterpret_cast<unsigned int*>(&h01);
    H.y = *reinterpret_cast<unsigned int*>(&h23);
    L.x = *reinterpret_cast<unsigned int*>(&l01);
    L.y = *reinterpret_cast<unsigned int*>(&l23);
    hi[i] = H;
    lo[i] = L;
}

// ---------------- bf16x3 GEMM via mma.sync (HMMA) ----------------
// C[M,N] = A[M,K] @ W[N,K]^T + bias ; A = Ah+Al, W = Wh+Wl
// CTA tile 128x128, K-chunk 64 (128B rows, SW128 swizzle), 3-stage cp.async.
// Single barrier per chunk; prefetch issued after barrier so copies overlap MMAs.
#define GBM 128
#define GBN 128
#define GBK 64
#define KDIM DMODEL
#define NCHUNK (KDIM/GBK)      // 16
#define STAGE_BYTES 65536      // Ah 16K | Al 16K | Bh 16K | Bl 16K
#define A_HI 0
#define A_LO 16384
#define B_HI 32768
#define B_LO 49152
#define NSTAGE 3
#define GSMEM_TOTAL (NSTAGE*STAGE_BYTES)   // 196608

__global__ void __launch_bounds__(256, 1) gemm_bf16x3(
    const __nv_bfloat16* __restrict__ Ah, const __nv_bfloat16* __restrict__ Al,
    const __nv_bfloat16* __restrict__ Wh, const __nv_bfloat16* __restrict__ Wl,
    const float* __restrict__ bias, float* __restrict__ C)
{
    extern __shared__ char smem[];
    const uint32_t sb = smem_u32(smem);
    const int tid = threadIdx.x;
    const int m0 = blockIdx.y * GBM;
    const int n0 = blockIdx.x * GBN;

    // warp layout: 4 (m) x 2 (n), warp tile 32 x 64
    const int l  = tid & 31;
    const int w  = tid >> 5;
    const int wm = (w & 3) * 32;
    const int wn = (w >> 2) * 64;

    const int rowA  = (l & 7) + ((l >> 3) & 1) * 8;
    const int kselA = (l >> 4) & 1;
    const int rowB  = (l & 7) + ((l >> 4) & 1) * 8;
    const int kselB = (l >> 3) & 1;

    float acc[2][8][4];
#pragma unroll
    for (int a = 0; a < 2; a++)
#pragma unroll
        for (int b = 0; b < 8; b++)
#pragma unroll
            for (int c = 0; c < 4; c++) acc[a][b][c] = 0.0f;

    auto load_chunk = [&](int st, int c) {
        uint32_t base = sb + st * STAGE_BYTES;
        int k0 = c * GBK;
#pragma unroll
        for (int it = 0; it < 4; it++) {
            int idx = tid + it * 256;
            int r  = idx >> 3;
            int ch = idx & 7;
            uint32_t sw = (uint32_t)(r * 128 + ((ch ^ (r & 7)) * 16));
            size_t gA = (size_t)(m0 + r) * KDIM + k0 + ch * 8;
            size_t gB = (size_t)(n0 + r) * KDIM + k0 + ch * 8;
            CP_ASYNC16(base + A_HI + sw, Ah + gA);
            CP_ASYNC16(base + A_LO + sw, Al + gA);
            CP_ASYNC16(base + B_HI + sw, Wh + gB);
            CP_ASYNC16(base + B_LO + sw, Wl + gB);
        }
    };

    // compute one K-chunk (4 k16 steps); products outermost per step for acc ILP
    auto compute_chunk = [&](int st) {
        uint32_t base = sb + st * STAGE_BYTES;
#pragma unroll
        for (int s = 0; s < 4; s++) {
            uint32_t a_h[2][4], a_l[2][4], b_h[4][4], b_l[4][4];
#pragma unroll
            for (int mt = 0; mt < 2; mt++) {
                int row = wm + mt * 16 + rowA;
                int ch  = (s * 2 + kselA) ^ (row & 7);
                uint32_t off = (uint32_t)(row * 128 + ch * 16);
                LDSM_X4(a_h[mt], base + A_HI + off);
                LDSM_X4(a_l[mt], base + A_LO + off);
            }
#pragma unroll
            for (int ng = 0; ng < 4; ng++) {
                int row = wn + ng * 16 + rowB;
                int ch  = (s * 2 + kselB) ^ (row & 7);
                uint32_t off = (uint32_t)(row * 128 + ch * 16);
                LDSM_X4(b_h[ng], base + B_HI + off);
                LDSM_X4(b_l[ng], base + B_LO + off);
            }
            // p0: Ah*Bh  p1: Ah*Bl  p2: Al*Bh — 16 independent MMAs between
            // consecutive writes to the same accumulator.
#pragma unroll
            for (int p = 0; p < 3; p++) {
#pragma unroll
                for (int mt = 0; mt < 2; mt++) {
#pragma unroll
                    for (int ng = 0; ng < 4; ng++) {
                        const uint32_t* A = (p == 2) ? a_l[mt] : a_h[mt];
                        const uint32_t* B = (p == 1) ? b_l[ng] : b_h[ng];
                        mma16816(acc[mt][ng * 2 + 0], A, &B[0]);
                        mma16816(acc[mt][ng * 2 + 1], A, &B[2]);
                    }
                }
            }
        }
    };

    load_chunk(0, 0); CP_COMMIT();
    load_chunk(1, 1); CP_COMMIT();

    for (int c = 0; c < NCHUNK; c++) {
        int st = c % NSTAGE;
        if (c + 2 < NCHUNK) { CP_WAIT(1); } else { CP_WAIT(0); }
        __syncthreads();                       // all warps done with stage (c-1)
        if (c + 2 < NCHUNK) {                  // prefetch overlaps compute below
            load_chunk((c + 2) % NSTAGE, c + 2); CP_COMMIT();
        }
        compute_chunk(st);
    }

    // epilogue: add bias, store fp32
    const int g  = l >> 2;
    const int tg = l & 3;
#pragma unroll
    for (int mt = 0; mt < 2; mt++) {
#pragma unroll
        for (int nt = 0; nt < 8; nt++) {
            int n = n0 + wn + nt * 8 + tg * 2;
            float bx = bias[n], by = bias[n + 1];
            int mA = m0 + wm + mt * 16 + g;
            float2 lo = make_float2(acc[mt][nt][0] + bx, acc[mt][nt][1] + by);
            float2 hi = make_float2(acc[mt][nt][2] + bx, acc[mt][nt][3] + by);
            *(float2*)(C + (size_t)mA * DMODEL + n)       = lo;
            *(float2*)(C + (size_t)(mA + 8) * DMODEL + n) = hi;
        }
    }
}

// ---------------- per-token attention (2 tokens / 128-thread block) --------
// Writes output directly as bf16 hi/lo splits (A-operand of the O-projection).
__global__ __launch_bounds__(128) void attn_per_token(
    const float* __restrict__ q, const float* __restrict__ k,
    const float* __restrict__ v,
    __nv_bfloat16* __restrict__ aoh, __nv_bfloat16* __restrict__ aol)
{
    const int half = threadIdx.x >> 6;
    const int t = blockIdx.x * 2 + half;
    const int i = threadIdx.x & 63;

    __shared__ float sk[2][DMODEL];
    __shared__ float sv[2][DMODEL];

    const float* kt = k + (size_t)t * DMODEL;
    const float* vt = v + (size_t)t * DMODEL;
#pragma unroll
    for (int f = i; f < 256; f += 64) {
        ((float4*)sk[half])[f] = ((const float4*)kt)[f];
        ((float4*)sv[half])[f] = ((const float4*)vt)[f];
    }
    __syncthreads();

    float qi[NHEAD];
    const float* qt = q + (size_t)t * DMODEL + i * NHEAD;
#pragma unroll
    for (int h4 = 0; h4 < NHEAD; h4 += 4) {
        float4 tq = *(const float4*)(qt + h4);
        qi[h4 + 0] = tq.x; qi[h4 + 1] = tq.y; qi[h4 + 2] = tq.z; qi[h4 + 3] = tq.w;
    }

    float sc[DH];
#pragma unroll
    for (int j = 0; j < DH; j++) {
        float s = 0.0f;
#pragma unroll
        for (int h = 0; h < NHEAD; h++)
            s = fmaf(qi[h], sk[half][j * NHEAD + h], s);
        sc[j] = s * 32.0f;   // * sqrt(D) — faithful quirk
    }

    float mx = sc[0];
#pragma unroll
    for (int j = 1; j < DH; j++) mx = fmaxf(mx, sc[j]);
    float sum = 0.0f;
#pragma unroll
    for (int j = 0; j < DH; j++) { sc[j] = __expf(sc[j] - mx); sum += sc[j]; }
    const float inv = 1.0f / sum;

    float o[NHEAD];
#pragma unroll
    for (int h = 0; h < NHEAD; h++) o[h] = 0.0f;
#pragma unroll
    for (int j = 0; j < DH; j++) {
        float a = sc[j] * inv;
#pragma unroll
        for (int h = 0; h < NHEAD; h++)
            o[h] = fmaf(a, sv[half][j * NHEAD + h], o[h]);
    }

    // split epilogue: 16 fp32 -> 8x(bf16x2 hi) + 8x(bf16x2 lo), two 16B stores each
    uint32_t hi8[8], lo8[8];
#pragma unroll
    for (int p = 0; p < 8; p++) {
        float x = o[2 * p], y = o[2 * p + 1];
        __nv_bfloat162 h2 = __floats2bfloat162_rn(x, y);
        float2 hf = __bfloat1622float2(h2);
        __nv_bfloat162 l2 = __floats2bfloat162_rn(x - hf.x, y - hf.y);
        hi8[p] = *reinterpret_cast<uint32_t*>(&h2);
        lo8[p] = *reinterpret_cast<uint32_t*>(&l2);
    }
    size_t obase = (size_t)t * DMODEL + i * NHEAD;
    uint4 H0 = make_uint4(hi8[0], hi8[1], hi8[2], hi8[3]);
    uint4 H1 = make_uint4(hi8[4], hi8[5], hi8[6], hi8[7]);
    uint4 L0 = make_uint4(lo8[0], lo8[1], lo8[2], lo8[3]);
    uint4 L1 = make_uint4(lo8[4], lo8[5], lo8[6], lo8[7]);
    *(uint4*)(aoh + obase)     = H0;
    *(uint4*)(aoh + obase + 8) = H1;
    *(uint4*)(aol + obase)     = L0;
    *(uint4*)(aol + obase + 8) = L1;
}

// ---------------- launch ----------------
extern "C" void kernel_launch(void* const* d_in, const int* in_sizes, int n_in,
                              void* d_out, int out_size)
{
    const float* query = (const float*)d_in[0];
    const float* key_  = (const float*)d_in[1];
    const float* value = (const float*)d_in[2];
    const float* Wq    = (const float*)d_in[3];
    const float* bq    = (const float*)d_in[4];
    const float* Wk    = (const float*)d_in[5];
    const float* bk    = (const float*)d_in[6];
    const float* Wv    = (const float*)d_in[7];
    const float* bv    = (const float*)d_in[8];
    const float* Wo    = (const float*)d_in[9];
    const float* bo    = (const float*)d_in[10];
    float* out = (float*)d_out;

    float *q, *k, *v;
    __nv_bfloat16 *xh, *xl, *wh, *wl;
    cudaGetSymbolAddress((void**)&q,  g_q);
    cudaGetSymbolAddress((void**)&k,  g_k);
    cudaGetSymbolAddress((void**)&v,  g_v);
    cudaGetSymbolAddress((void**)&xh, g_xh);
    cudaGetSymbolAddress((void**)&xl, g_xl);
    cudaGetSymbolAddress((void**)&wh, g_wh);
    cudaGetSymbolAddress((void**)&wl, g_wl);

    cudaFuncSetAttribute(gemm_bf16x3, cudaFuncAttributeMaxDynamicSharedMemorySize, GSMEM_TOTAL);

    const int nAct4 = MTOK * DMODEL / 4;
    const int nW4   = DMODEL * DMODEL / 4;
    dim3 cblkA((nAct4 + 255) / 256), cblkW((nW4 + 255) / 256);
    dim3 ggrid(DMODEL / GBN, MTOK / GBM);   // (8, 128)

    // Q projection
    split_bf16_kernel<<<cblkA, 256>>>((const float4*)query, (uint2*)xh, (uint2*)xl, nAct4);
    split_bf16_kernel<<<cblkW, 256>>>((const float4*)Wq, (uint2*)wh, (uint2*)wl, nW4);
    gemm_bf16x3<<<ggrid, 256, GSMEM_TOTAL>>>(xh, xl, wh, wl, bq, q);
    // K projection
    split_bf16_kernel<<<cblkA, 256>>>((const float4*)key_, (uint2*)xh, (uint2*)xl, nAct4);
    split_bf16_kernel<<<cblkW, 256>>>((const float4*)Wk, (uint2*)wh, (uint2*)wl, nW4);
    gemm_bf16x3<<<ggrid, 256, GSMEM_TOTAL>>>(xh, xl, wh, wl, bk, k);
    // V projection
    split_bf16_kernel<<<cblkA, 256>>>((const float4*)value, (uint2*)xh, (uint2*)xl, nAct4);
    split_bf16_kernel<<<cblkW, 256>>>((const float4*)Wv, (uint2*)wh, (uint2*)wl, nW4);
    gemm_bf16x3<<<ggrid, 256, GSMEM_TOTAL>>>(xh, xl, wh, wl, bv, v);

    // attention: writes ao hi/lo splits directly into xh/xl (O-gemm A operand)
    attn_per_token<<<MTOK / 2, 128>>>(q, k, v, xh, xl);

    // output projection (no activation split kernel needed)
    split_bf16_kernel<<<cblkW, 256>>>((const float4*)Wo, (uint2*)wh, (uint2*)wl, nW4);
    gemm_bf16x3<<<ggrid, 256, GSMEM_TOTAL>>>(xh, xl, wh, wl, bo, out);
}